// round 13
// baseline (speedup 1.0000x reference)
#include <cuda_runtime.h>
#include <cuda_fp16.h>
#include <cstdint>

#define N_NODES 50000
#define F_IN    256
#define F_OUT   64
#define N_EDGES 800000

#define BCAP     64          // bucket capacity per row (P(overflow) ~ 1e-20, clamped)
#define NGB      391         // GEMM blocks: ceil(50000/128)
#define NFB      782         // fill blocks: ceil(800000/4/256)

// ---- device scratch (allocation-free) ----
// __align__(16): gather does LDG.128 on g_xwh; __half only guarantees 2 B
// alignment and a misaligned wide load traps (err715).
__device__ __align__(16) __half g_xwh[(size_t)N_NODES * F_OUT];   // XW fp16, 6.4 MB
__device__ int    g_cnt[N_NODES];                                 // per-row degree/cursor
__device__ __align__(16) int2 g_bucket[(size_t)N_NODES * BCAP];   // 25.6 MB buckets

// ===========================================================================
// Fused kernel: blocks [0, NGB) run the TF32 GEMM (register double-buffered),
// blocks [NGB, NGB+NFB) run the single-pass bucket fill.
// ===========================================================================
#define GTM 128
#define GTK 32
#define XS_STR 36
#define WS_STR 72

__device__ __forceinline__ float f2tf32f(float f) {
    uint32_t u;
    asm("cvt.rna.tf32.f32 %0, %1;" : "=r"(u) : "f"(f));
    return __uint_as_float(u);
}
__device__ __forceinline__ float4 cvt4(float4 v) {
    v.x = f2tf32f(v.x); v.y = f2tf32f(v.y);
    v.z = f2tf32f(v.z); v.w = f2tf32f(v.w);
    return v;
}

__device__ __forceinline__ void fill_edges(int e0,
                                           const int* __restrict__ erow,
                                           const int* __restrict__ ecol,
                                           const float* __restrict__ evals) {
    if (e0 + 3 < N_EDGES) {
        const int4   r = *(const int4*)(erow + e0);
        const int4   c = *(const int4*)(ecol + e0);
        const float4 v = *(const float4*)(evals + e0);

        int p0 = atomicAdd(&g_cnt[r.x], 1);
        int p1 = atomicAdd(&g_cnt[r.y], 1);
        int p2 = atomicAdd(&g_cnt[r.z], 1);
        int p3 = atomicAdd(&g_cnt[r.w], 1);

        if (p0 < BCAP) g_bucket[(size_t)r.x * BCAP + p0] = make_int2(c.x, __float_as_int(v.x));
        if (p1 < BCAP) g_bucket[(size_t)r.y * BCAP + p1] = make_int2(c.y, __float_as_int(v.y));
        if (p2 < BCAP) g_bucket[(size_t)r.z * BCAP + p2] = make_int2(c.z, __float_as_int(v.z));
        if (p3 < BCAP) g_bucket[(size_t)r.w * BCAP + p3] = make_int2(c.w, __float_as_int(v.w));
    } else {
        for (int e = e0; e < N_EDGES; e++) {
            int r = __ldg(erow + e);
            int p = atomicAdd(&g_cnt[r], 1);
            if (p < BCAP)
                g_bucket[(size_t)r * BCAP + p] =
                    make_int2(__ldg(ecol + e), __float_as_int(__ldg(evals + e)));
        }
    }
}

__global__ __launch_bounds__(256) void fused_gemm_fill_kernel(
        const float* __restrict__ X, const float* __restrict__ W,
        const int* __restrict__ erow, const int* __restrict__ ecol,
        const float* __restrict__ evals) {
    if (blockIdx.x >= NGB) {
        const int t = (blockIdx.x - NGB) * blockDim.x + threadIdx.x;
        fill_edges(t * 4, erow, ecol, evals);
        return;
    }

    __shared__ float Xs[GTM][XS_STR];
    __shared__ float Ws[GTK][WS_STR];

    const int tid  = threadIdx.x;
    const int warp = tid >> 5;
    const int lane = tid & 31;
    const int rowBase = blockIdx.x * GTM;
    const int qid  = lane >> 2;
    const int qsub = lane & 3;

    int wr[2], wc[2], xr[4], xc[4];
#pragma unroll
    for (int i = 0; i < 2; i++) { int idx = tid + i * 256; wr[i] = idx >> 4; wc[i] = idx & 15; }
#pragma unroll
    for (int i = 0; i < 4; i++) { int idx = tid + i * 256; xr[i] = idx >> 3; xc[i] = idx & 7; }

    float4 rw[2], rx[4];
#pragma unroll
    for (int i = 0; i < 2; i++)
        rw[i] = *(const float4*)(W + (size_t)wr[i] * F_OUT + wc[i] * 4);
#pragma unroll
    for (int i = 0; i < 4; i++) {
        int gr = rowBase + xr[i];
        rx[i] = make_float4(0.f, 0.f, 0.f, 0.f);
        if (gr < N_NODES)
            rx[i] = *(const float4*)(X + (size_t)gr * F_IN + xc[i] * 4);
    }

    float acc[8][4];
#pragma unroll
    for (int j = 0; j < 8; j++)
#pragma unroll
        for (int i = 0; i < 4; i++) acc[j][i] = 0.0f;

#pragma unroll 1
    for (int c = 0; c < F_IN / GTK; c++) {
#pragma unroll
        for (int i = 0; i < 2; i++) *(float4*)&Ws[wr[i]][wc[i] * 4] = cvt4(rw[i]);
#pragma unroll
        for (int i = 0; i < 4; i++) *(float4*)&Xs[xr[i]][xc[i] * 4] = cvt4(rx[i]);
        __syncthreads();

        if (c + 1 < F_IN / GTK) {
            const int k0 = (c + 1) * GTK;
#pragma unroll
            for (int i = 0; i < 2; i++)
                rw[i] = *(const float4*)(W + (size_t)(k0 + wr[i]) * F_OUT + wc[i] * 4);
#pragma unroll
            for (int i = 0; i < 4; i++) {
                int gr = rowBase + xr[i];
                if (gr < N_NODES)
                    rx[i] = *(const float4*)(X + (size_t)gr * F_IN + k0 + xc[i] * 4);
            }
        }

#pragma unroll
        for (int kk = 0; kk < GTK; kk += 8) {
            const int ar = warp * 16 + qid;
            const uint32_t a0 = __float_as_uint(Xs[ar    ][kk + qsub    ]);
            const uint32_t a1 = __float_as_uint(Xs[ar + 8][kk + qsub    ]);
            const uint32_t a2 = __float_as_uint(Xs[ar    ][kk + qsub + 4]);
            const uint32_t a3 = __float_as_uint(Xs[ar + 8][kk + qsub + 4]);
#pragma unroll
            for (int j = 0; j < 8; j++) {
                const uint32_t b0 = __float_as_uint(Ws[kk + qsub    ][j * 8 + qid]);
                const uint32_t b1 = __float_as_uint(Ws[kk + qsub + 4][j * 8 + qid]);
                asm volatile(
                    "mma.sync.aligned.m16n8k8.row.col.f32.tf32.tf32.f32 "
                    "{%0,%1,%2,%3}, {%4,%5,%6,%7}, {%8,%9}, {%0,%1,%2,%3};"
                    : "+f"(acc[j][0]), "+f"(acc[j][1]), "+f"(acc[j][2]), "+f"(acc[j][3])
                    : "r"(a0), "r"(a1), "r"(a2), "r"(a3), "r"(b0), "r"(b1));
            }
        }
        __syncthreads();
    }

    const int crow = rowBase + warp * 16 + qid;
#pragma unroll
    for (int j = 0; j < 8; j++) {
        const int ccol = j * 8 + 2 * qsub;
        if (crow < N_NODES)
            *(__half2*)(g_xwh + (size_t)crow * F_OUT + ccol) =
                __floats2half2_rn(acc[j][0], acc[j][1]);
        if (crow + 8 < N_NODES)
            *(__half2*)(g_xwh + (size_t)(crow + 8) * F_OUT + ccol) =
                __floats2half2_rn(acc[j][2], acc[j][3]);
    }
}

// ===========================================================================
// Gather v3: one warp per row, 4 groups x 8 lanes, uint4 slices.
// 4-deep software pipeline: a group issues ALL FOUR of its edges' entry loads
// then all four row loads before any math -> 8 loads in flight per warp and
// one exposed L2 round per deg<=16 row (instead of two).
// ===========================================================================
__device__ __forceinline__ void acc_edge(float* acc, const int2 e, const int s) {
    const uint4 h = *(const uint4*)(g_xwh + (size_t)e.x * F_OUT + s * 8);
    const float v = __int_as_float(e.y);
    const __half2* p = (const __half2*)&h;
#pragma unroll
    for (int k = 0; k < 4; k++) {
        const float2 f = __half22float2(p[k]);
        acc[2 * k]     += v * f.x;
        acc[2 * k + 1] += v * f.y;
    }
}

__global__ __launch_bounds__(256) void gather_kernel(float* __restrict__ out) {
    const int row  = (blockIdx.x * blockDim.x + threadIdx.x) >> 5;
    const int lane = threadIdx.x & 31;
    if (row >= N_NODES) return;

    const int g = lane >> 3;    // edge group 0..3
    const int s = lane & 7;     // col slice: halves [s*8, s*8+8)

    int deg = __ldg(&g_cnt[row]);
    deg = deg < BCAP ? deg : BCAP;
    const int2* __restrict__ bkt = g_bucket + (size_t)row * BCAP;

    float acc[8];
#pragma unroll
    for (int k = 0; k < 8; k++) acc[k] = 0.0f;

    int i = g;
    // 4-deep: covers the whole group share of a deg<=16 row in one round
    for (; i + 12 < deg; i += 16) {
        const int2 e0 = bkt[i];
        const int2 e1 = bkt[i + 4];
        const int2 e2 = bkt[i + 8];
        const int2 e3 = bkt[i + 12];
        const uint4 h0 = *(const uint4*)(g_xwh + (size_t)e0.x * F_OUT + s * 8);
        const uint4 h1 = *(const uint4*)(g_xwh + (size_t)e1.x * F_OUT + s * 8);
        const uint4 h2 = *(const uint4*)(g_xwh + (size_t)e2.x * F_OUT + s * 8);
        const uint4 h3 = *(const uint4*)(g_xwh + (size_t)e3.x * F_OUT + s * 8);
        const float v0 = __int_as_float(e0.y), v1 = __int_as_float(e1.y);
        const float v2 = __int_as_float(e2.y), v3 = __int_as_float(e3.y);
        const __half2* p0 = (const __half2*)&h0;
        const __half2* p1 = (const __half2*)&h1;
        const __half2* p2 = (const __half2*)&h2;
        const __half2* p3 = (const __half2*)&h3;
#pragma unroll
        for (int k = 0; k < 4; k++) {
            const float2 f0 = __half22float2(p0[k]);
            const float2 f1 = __half22float2(p1[k]);
            const float2 f2 = __half22float2(p2[k]);
            const float2 f3 = __half22float2(p3[k]);
            acc[2 * k]     += v0 * f0.x + v1 * f1.x + v2 * f2.x + v3 * f3.x;
            acc[2 * k + 1] += v0 * f0.y + v1 * f1.y + v2 * f2.y + v3 * f3.y;
        }
    }
    // 2-deep remainder
    for (; i + 4 < deg; i += 8) {
        const int2 ea = bkt[i];
        const int2 eb = bkt[i + 4];
        acc_edge(acc, ea, s);
        acc_edge(acc, eb, s);
    }
    // single tail
    if (i < deg) acc_edge(acc, bkt[i], s);

    // fold the 4 group-partials (lanes s, s+8, s+16, s+24 hold same col slice)
#pragma unroll
    for (int m = 8; m <= 16; m <<= 1)
#pragma unroll
        for (int k = 0; k < 8; k++)
            acc[k] += __shfl_xor_sync(0xffffffffu, acc[k], m);

    if (g == 0) {
        float* dst = out + (size_t)row * F_OUT + s * 8;
        *(float4*)(dst)     = make_float4(acc[0], acc[1], acc[2], acc[3]);
        *(float4*)(dst + 4) = make_float4(acc[4], acc[5], acc[6], acc[7]);
    }
}

// ===========================================================================
// Launch: memset counts -> fused (GEMM || fill) -> gather.  3 graph nodes.
// ===========================================================================
extern "C" void kernel_launch(void* const* d_in, const int* in_sizes, int n_in,
                              void* d_out, int out_size) {
    const float* X     = (const float*)d_in[0];
    const float* W     = (const float*)d_in[1];
    const int*   erow  = (const int*)d_in[2];
    const int*   ecol  = (const int*)d_in[3];
    const float* evals = (const float*)d_in[4];
    float* out = (float*)d_out;

    void* cnt_ptr = nullptr;
    cudaGetSymbolAddress(&cnt_ptr, g_cnt);
    cudaMemsetAsync(cnt_ptr, 0, N_NODES * sizeof(int));

    fused_gemm_fill_kernel<<<NGB + NFB, 256>>>(X, W, erow, ecol, evals);
    gather_kernel<<<(N_NODES * 32 + 255) / 256, 256>>>(out);
}

// round 14
// speedup vs baseline: 1.0637x; 1.0637x over previous
#include <cuda_runtime.h>
#include <cuda_fp16.h>
#include <cstdint>

#define N_NODES 50000
#define F_IN    256
#define F_OUT   64
#define N_EDGES 800000

#define BCAP     64          // bucket capacity per row (P(overflow) ~ 1e-20, clamped)
#define NGB      391         // GEMM blocks: ceil(50000/128)
#define NFB      782         // fill blocks: ceil(800000/4/256)

// ---- device scratch (allocation-free) ----
// __align__(16): wide loads on these symbols trap (err715) if misaligned.
__device__ __align__(16) __half g_xwh[(size_t)N_NODES * F_OUT];   // XW fp16, 6.4 MB
__device__ int    g_cnt[N_NODES];                                 // per-row degree/cursor
__device__ __align__(16) int2 g_bucket[(size_t)N_NODES * BCAP];   // 25.6 MB buckets

// ===========================================================================
// Fused kernel: blocks [0, NGB) run the TF32 GEMM (register double-buffered),
// blocks [NGB, NGB+NFB) run the single-pass bucket fill.
// ===========================================================================
#define GTM 128
#define GTK 32
#define XS_STR 36
#define WS_STR 72

__device__ __forceinline__ float f2tf32f(float f) {
    uint32_t u;
    asm("cvt.rna.tf32.f32 %0, %1;" : "=r"(u) : "f"(f));
    return __uint_as_float(u);
}
__device__ __forceinline__ float4 cvt4(float4 v) {
    v.x = f2tf32f(v.x); v.y = f2tf32f(v.y);
    v.z = f2tf32f(v.z); v.w = f2tf32f(v.w);
    return v;
}

__device__ __forceinline__ void fill_edges(int e0,
                                           const int* __restrict__ erow,
                                           const int* __restrict__ ecol,
                                           const float* __restrict__ evals) {
    if (e0 + 3 < N_EDGES) {
        const int4   r = *(const int4*)(erow + e0);
        const int4   c = *(const int4*)(ecol + e0);
        const float4 v = *(const float4*)(evals + e0);

        int p0 = atomicAdd(&g_cnt[r.x], 1);
        int p1 = atomicAdd(&g_cnt[r.y], 1);
        int p2 = atomicAdd(&g_cnt[r.z], 1);
        int p3 = atomicAdd(&g_cnt[r.w], 1);

        if (p0 < BCAP) g_bucket[(size_t)r.x * BCAP + p0] = make_int2(c.x, __float_as_int(v.x));
        if (p1 < BCAP) g_bucket[(size_t)r.y * BCAP + p1] = make_int2(c.y, __float_as_int(v.y));
        if (p2 < BCAP) g_bucket[(size_t)r.z * BCAP + p2] = make_int2(c.z, __float_as_int(v.z));
        if (p3 < BCAP) g_bucket[(size_t)r.w * BCAP + p3] = make_int2(c.w, __float_as_int(v.w));
    } else {
        for (int e = e0; e < N_EDGES; e++) {
            int r = __ldg(erow + e);
            int p = atomicAdd(&g_cnt[r], 1);
            if (p < BCAP)
                g_bucket[(size_t)r * BCAP + p] =
                    make_int2(__ldg(ecol + e), __float_as_int(__ldg(evals + e)));
        }
    }
}

__global__ __launch_bounds__(256) void fused_gemm_fill_kernel(
        const float* __restrict__ X, const float* __restrict__ W,
        const int* __restrict__ erow, const int* __restrict__ ecol,
        const float* __restrict__ evals) {
    if (blockIdx.x >= NGB) {
        const int t = (blockIdx.x - NGB) * blockDim.x + threadIdx.x;
        fill_edges(t * 4, erow, ecol, evals);
        return;
    }

    __shared__ float Xs[GTM][XS_STR];
    __shared__ float Ws[GTK][WS_STR];

    const int tid  = threadIdx.x;
    const int warp = tid >> 5;
    const int lane = tid & 31;
    const int rowBase = blockIdx.x * GTM;
    const int qid  = lane >> 2;
    const int qsub = lane & 3;

    int wr[2], wc[2], xr[4], xc[4];
#pragma unroll
    for (int i = 0; i < 2; i++) { int idx = tid + i * 256; wr[i] = idx >> 4; wc[i] = idx & 15; }
#pragma unroll
    for (int i = 0; i < 4; i++) { int idx = tid + i * 256; xr[i] = idx >> 3; xc[i] = idx & 7; }

    float4 rw[2], rx[4];
#pragma unroll
    for (int i = 0; i < 2; i++)
        rw[i] = *(const float4*)(W + (size_t)wr[i] * F_OUT + wc[i] * 4);
#pragma unroll
    for (int i = 0; i < 4; i++) {
        int gr = rowBase + xr[i];
        rx[i] = make_float4(0.f, 0.f, 0.f, 0.f);
        if (gr < N_NODES)
            rx[i] = *(const float4*)(X + (size_t)gr * F_IN + xc[i] * 4);
    }

    float acc[8][4];
#pragma unroll
    for (int j = 0; j < 8; j++)
#pragma unroll
        for (int i = 0; i < 4; i++) acc[j][i] = 0.0f;

#pragma unroll 1
    for (int c = 0; c < F_IN / GTK; c++) {
#pragma unroll
        for (int i = 0; i < 2; i++) *(float4*)&Ws[wr[i]][wc[i] * 4] = cvt4(rw[i]);
#pragma unroll
        for (int i = 0; i < 4; i++) *(float4*)&Xs[xr[i]][xc[i] * 4] = cvt4(rx[i]);
        __syncthreads();

        if (c + 1 < F_IN / GTK) {
            const int k0 = (c + 1) * GTK;
#pragma unroll
            for (int i = 0; i < 2; i++)
                rw[i] = *(const float4*)(W + (size_t)(k0 + wr[i]) * F_OUT + wc[i] * 4);
#pragma unroll
            for (int i = 0; i < 4; i++) {
                int gr = rowBase + xr[i];
                if (gr < N_NODES)
                    rx[i] = *(const float4*)(X + (size_t)gr * F_IN + k0 + xc[i] * 4);
            }
        }

#pragma unroll
        for (int kk = 0; kk < GTK; kk += 8) {
            const int ar = warp * 16 + qid;
            const uint32_t a0 = __float_as_uint(Xs[ar    ][kk + qsub    ]);
            const uint32_t a1 = __float_as_uint(Xs[ar + 8][kk + qsub    ]);
            const uint32_t a2 = __float_as_uint(Xs[ar    ][kk + qsub + 4]);
            const uint32_t a3 = __float_as_uint(Xs[ar + 8][kk + qsub + 4]);
#pragma unroll
            for (int j = 0; j < 8; j++) {
                const uint32_t b0 = __float_as_uint(Ws[kk + qsub    ][j * 8 + qid]);
                const uint32_t b1 = __float_as_uint(Ws[kk + qsub + 4][j * 8 + qid]);
                asm volatile(
                    "mma.sync.aligned.m16n8k8.row.col.f32.tf32.tf32.f32 "
                    "{%0,%1,%2,%3}, {%4,%5,%6,%7}, {%8,%9}, {%0,%1,%2,%3};"
                    : "+f"(acc[j][0]), "+f"(acc[j][1]), "+f"(acc[j][2]), "+f"(acc[j][3])
                    : "r"(a0), "r"(a1), "r"(a2), "r"(a3), "r"(b0), "r"(b1));
            }
        }
        __syncthreads();
    }

    const int crow = rowBase + warp * 16 + qid;
#pragma unroll
    for (int j = 0; j < 8; j++) {
        const int ccol = j * 8 + 2 * qsub;
        if (crow < N_NODES)
            *(__half2*)(g_xwh + (size_t)crow * F_OUT + ccol) =
                __floats2half2_rn(acc[j][0], acc[j][1]);
        if (crow + 8 < N_NODES)
            *(__half2*)(g_xwh + (size_t)(crow + 8) * F_OUT + ccol) =
                __floats2half2_rn(acc[j][2], acc[j][3]);
    }
}

// ===========================================================================
// Gather v4: one warp per row; lane owns cols [2*lane, 2*lane+1].
// Row's bucket entries staged into SMEM with ONE coalesced warp load, then
// read back via LDS broadcast -> every XW row load is chain-free/independent.
// ===========================================================================
__global__ __launch_bounds__(256) void gather_kernel(float* __restrict__ out) {
    __shared__ int2 sent[8][32];   // per-warp entry stage (2 KB/block)

    const int w    = threadIdx.x >> 5;
    const int lane = threadIdx.x & 31;
    const int row  = (blockIdx.x * blockDim.x + threadIdx.x) >> 5;
    if (row >= N_NODES) return;   // warp-uniform exit

    int deg = __ldg(&g_cnt[row]);
    deg = deg < BCAP ? deg : BCAP;
    const int2* __restrict__ bkt = g_bucket + (size_t)row * BCAP;
    const int col = lane * 2;

    float2 acc = make_float2(0.f, 0.f);

    for (int base = 0; base < deg; base += 32) {
        const int m = (deg - base) < 32 ? (deg - base) : 32;
        if (lane < m) sent[w][lane] = bkt[base + lane];
        __syncwarp();

        int i = 0;
        for (; i + 4 <= m; i += 4) {
            // entries from LDS (broadcast, 29 cyc); 4 independent row LDG.64s
            const int2 e0 = sent[w][i];
            const int2 e1 = sent[w][i + 1];
            const int2 e2 = sent[w][i + 2];
            const int2 e3 = sent[w][i + 3];
            const __half2 h0 = *(const __half2*)(g_xwh + (size_t)e0.x * F_OUT + col);
            const __half2 h1 = *(const __half2*)(g_xwh + (size_t)e1.x * F_OUT + col);
            const __half2 h2 = *(const __half2*)(g_xwh + (size_t)e2.x * F_OUT + col);
            const __half2 h3 = *(const __half2*)(g_xwh + (size_t)e3.x * F_OUT + col);
            const float v0 = __int_as_float(e0.y), v1 = __int_as_float(e1.y);
            const float v2 = __int_as_float(e2.y), v3 = __int_as_float(e3.y);
            const float2 f0 = __half22float2(h0);
            const float2 f1 = __half22float2(h1);
            const float2 f2 = __half22float2(h2);
            const float2 f3 = __half22float2(h3);
            acc.x += v0 * f0.x + v1 * f1.x + v2 * f2.x + v3 * f3.x;
            acc.y += v0 * f0.y + v1 * f1.y + v2 * f2.y + v3 * f3.y;
        }
        for (; i < m; i++) {
            const int2 e = sent[w][i];
            const __half2 h = *(const __half2*)(g_xwh + (size_t)e.x * F_OUT + col);
            const float v = __int_as_float(e.y);
            const float2 f = __half22float2(h);
            acc.x += v * f.x;
            acc.y += v * f.y;
        }
        __syncwarp();   // before next chunk overwrites sent
    }

    *(float2*)(out + (size_t)row * F_OUT + col) = acc;   // 256 B/warp coalesced
}

// ===========================================================================
// Launch: memset counts -> fused (GEMM || fill) -> gather.  3 graph nodes.
// ===========================================================================
extern "C" void kernel_launch(void* const* d_in, const int* in_sizes, int n_in,
                              void* d_out, int out_size) {
    const float* X     = (const float*)d_in[0];
    const float* W     = (const float*)d_in[1];
    const int*   erow  = (const int*)d_in[2];
    const int*   ecol  = (const int*)d_in[3];
    const float* evals = (const float*)d_in[4];
    float* out = (float*)d_out;

    void* cnt_ptr = nullptr;
    cudaGetSymbolAddress(&cnt_ptr, g_cnt);
    cudaMemsetAsync(cnt_ptr, 0, N_NODES * sizeof(int));

    fused_gemm_fill_kernel<<<NGB + NFB, 256>>>(X, W, erow, ecol, evals);
    gather_kernel<<<(N_NODES * 32 + 255) / 256, 256>>>(out);
}

// round 15
// speedup vs baseline: 1.1034x; 1.0374x over previous
#include <cuda_runtime.h>
#include <cuda_fp16.h>
#include <cstdint>

#define N_NODES 50000
#define F_IN    256
#define F_OUT   64
#define N_EDGES 800000

#define BCAP     64          // bucket capacity per row (P(overflow) ~ 1e-20, clamped)
#define NGB      391         // GEMM blocks: ceil(50000/128)
#define NFB      782         // fill blocks: ceil(800000/4/256)

// ---- device scratch (allocation-free) ----
// __align__(16): wide loads on these symbols trap (err715) if misaligned.
__device__ __align__(16) __half g_xwh[(size_t)N_NODES * F_OUT];   // XW fp16, 6.4 MB
__device__ int    g_cnt[N_NODES];                                 // per-row degree/cursor
__device__ __align__(16) int2 g_bucket[(size_t)N_NODES * BCAP];   // 25.6 MB buckets

// ===========================================================================
// Fused kernel: blocks [0, NGB) run an FP16 tensor-core GEMM (m16n8k16,
// fp32 accum, register double-buffered); blocks [NGB, NGB+NFB) run the
// single-pass bucket fill. ~14 KB smem -> more resident fill blocks.
// ===========================================================================
#define GTM 128
#define GTK 32
#define XH_STR 36   // halves per row: 72 B (8B-aligned stores, spread banks)
#define WH_STR 36

__device__ __forceinline__ void fill_edges(int e0,
                                           const int* __restrict__ erow,
                                           const int* __restrict__ ecol,
                                           const float* __restrict__ evals) {
    if (e0 + 3 < N_EDGES) {
        const int4   r = *(const int4*)(erow + e0);
        const int4   c = *(const int4*)(ecol + e0);
        const float4 v = *(const float4*)(evals + e0);

        int p0 = atomicAdd(&g_cnt[r.x], 1);
        int p1 = atomicAdd(&g_cnt[r.y], 1);
        int p2 = atomicAdd(&g_cnt[r.z], 1);
        int p3 = atomicAdd(&g_cnt[r.w], 1);

        if (p0 < BCAP) g_bucket[(size_t)r.x * BCAP + p0] = make_int2(c.x, __float_as_int(v.x));
        if (p1 < BCAP) g_bucket[(size_t)r.y * BCAP + p1] = make_int2(c.y, __float_as_int(v.y));
        if (p2 < BCAP) g_bucket[(size_t)r.z * BCAP + p2] = make_int2(c.z, __float_as_int(v.z));
        if (p3 < BCAP) g_bucket[(size_t)r.w * BCAP + p3] = make_int2(c.w, __float_as_int(v.w));
    } else {
        for (int e = e0; e < N_EDGES; e++) {
            int r = __ldg(erow + e);
            int p = atomicAdd(&g_cnt[r], 1);
            if (p < BCAP)
                g_bucket[(size_t)r * BCAP + p] =
                    make_int2(__ldg(ecol + e), __float_as_int(__ldg(evals + e)));
        }
    }
}

__global__ __launch_bounds__(256) void fused_gemm_fill_kernel(
        const float* __restrict__ X, const float* __restrict__ W,
        const int* __restrict__ erow, const int* __restrict__ ecol,
        const float* __restrict__ evals) {
    if (blockIdx.x >= NGB) {
        const int t = (blockIdx.x - NGB) * blockDim.x + threadIdx.x;
        fill_edges(t * 4, erow, ecol, evals);
        return;
    }

    __shared__ __half Xsh[GTM][XH_STR];   // 9216 B, k-major rows
    __shared__ __half Wsn[F_OUT][WH_STR]; // 4608 B, TRANSPOSED: [n][k]

    const int tid  = threadIdx.x;
    const int warp = tid >> 5;
    const int lane = tid & 31;
    const int rowBase = blockIdx.x * GTM;
    const int qid  = lane >> 2;   // 0..7
    const int qsub = lane & 3;    // 0..3

    int wr[2], wc[2], xr[4], xc[4];
#pragma unroll
    for (int i = 0; i < 2; i++) { int idx = tid + i * 256; wr[i] = idx >> 4; wc[i] = idx & 15; }
#pragma unroll
    for (int i = 0; i < 4; i++) { int idx = tid + i * 256; xr[i] = idx >> 3; xc[i] = idx & 7; }

    float4 rw[2], rx[4];
#pragma unroll
    for (int i = 0; i < 2; i++)
        rw[i] = *(const float4*)(W + (size_t)wr[i] * F_OUT + wc[i] * 4);
#pragma unroll
    for (int i = 0; i < 4; i++) {
        int gr = rowBase + xr[i];
        rx[i] = make_float4(0.f, 0.f, 0.f, 0.f);
        if (gr < N_NODES)
            rx[i] = *(const float4*)(X + (size_t)gr * F_IN + xc[i] * 4);
    }

    float acc[8][4];
#pragma unroll
    for (int j = 0; j < 8; j++)
#pragma unroll
        for (int i = 0; i < 4; i++) acc[j][i] = 0.0f;

#pragma unroll 1
    for (int c = 0; c < F_IN / GTK; c++) {
        // commit W chunk TRANSPOSED: Wsn[n][k] = W[k0+k][n]  (4x 2B stores each)
#pragma unroll
        for (int i = 0; i < 2; i++) {
            const int k = wr[i], n0 = wc[i] * 4;
            Wsn[n0 + 0][k] = __float2half_rn(rw[i].x);
            Wsn[n0 + 1][k] = __float2half_rn(rw[i].y);
            Wsn[n0 + 2][k] = __float2half_rn(rw[i].z);
            Wsn[n0 + 3][k] = __float2half_rn(rw[i].w);
        }
        // commit X chunk k-major as half (one 8 B store of 4 halves)
#pragma unroll
        for (int i = 0; i < 4; i++) {
            __half2 h01 = __floats2half2_rn(rx[i].x, rx[i].y);
            __half2 h23 = __floats2half2_rn(rx[i].z, rx[i].w);
            *(__half2*)&Xsh[xr[i]][xc[i] * 4]     = h01;
            *(__half2*)&Xsh[xr[i]][xc[i] * 4 + 2] = h23;
        }
        __syncthreads();

        // prefetch next chunk during MMA
        if (c + 1 < F_IN / GTK) {
            const int k0 = (c + 1) * GTK;
#pragma unroll
            for (int i = 0; i < 2; i++)
                rw[i] = *(const float4*)(W + (size_t)(k0 + wr[i]) * F_OUT + wc[i] * 4);
#pragma unroll
            for (int i = 0; i < 4; i++) {
                int gr = rowBase + xr[i];
                if (gr < N_NODES)
                    rx[i] = *(const float4*)(X + (size_t)gr * F_IN + k0 + xc[i] * 4);
            }
        }

        // 2 k-steps of 16 per 32-chunk
#pragma unroll
        for (int kk = 0; kk < GTK; kk += 16) {
            const int ar = warp * 16 + qid;
            const int ka = kk + 2 * qsub;
            const uint32_t a0 = *(const uint32_t*)&Xsh[ar    ][ka    ];
            const uint32_t a1 = *(const uint32_t*)&Xsh[ar + 8][ka    ];
            const uint32_t a2 = *(const uint32_t*)&Xsh[ar    ][ka + 8];
            const uint32_t a3 = *(const uint32_t*)&Xsh[ar + 8][ka + 8];
#pragma unroll
            for (int j = 0; j < 8; j++) {
                const int col = j * 8 + qid;
                const uint32_t b0 = *(const uint32_t*)&Wsn[col][ka    ];
                const uint32_t b1 = *(const uint32_t*)&Wsn[col][ka + 8];
                asm volatile(
                    "mma.sync.aligned.m16n8k16.row.col.f32.f16.f16.f32 "
                    "{%0,%1,%2,%3}, {%4,%5,%6,%7}, {%8,%9}, {%0,%1,%2,%3};"
                    : "+f"(acc[j][0]), "+f"(acc[j][1]), "+f"(acc[j][2]), "+f"(acc[j][3])
                    : "r"(a0), "r"(a1), "r"(a2), "r"(a3), "r"(b0), "r"(b1));
            }
        }
        __syncthreads();
    }

    const int crow = rowBase + warp * 16 + qid;
#pragma unroll
    for (int j = 0; j < 8; j++) {
        const int ccol = j * 8 + 2 * qsub;
        if (crow < N_NODES)
            *(__half2*)(g_xwh + (size_t)crow * F_OUT + ccol) =
                __floats2half2_rn(acc[j][0], acc[j][1]);
        if (crow + 8 < N_NODES)
            *(__half2*)(g_xwh + (size_t)(crow + 8) * F_OUT + ccol) =
                __floats2half2_rn(acc[j][2], acc[j][3]);
    }
}

// ===========================================================================
// Gather (v2, measured best 24.2us): one warp per row, 4 groups x 8 lanes;
// group g takes edges g, g+4, ...; each lane loads a uint4 (16 B) slice.
// fp32 accumulate; cross-group shfl fold.
// ===========================================================================
__global__ __launch_bounds__(256) void gather_kernel(float* __restrict__ out) {
    const int row  = (blockIdx.x * blockDim.x + threadIdx.x) >> 5;
    const int lane = threadIdx.x & 31;
    if (row >= N_NODES) return;

    const int g = lane >> 3;    // edge group 0..3
    const int s = lane & 7;     // col slice: halves [s*8, s*8+8)

    int deg = __ldg(&g_cnt[row]);
    deg = deg < BCAP ? deg : BCAP;
    const int2* __restrict__ bkt = g_bucket + (size_t)row * BCAP;

    float acc[8];
#pragma unroll
    for (int k = 0; k < 8; k++) acc[k] = 0.0f;

    int i = g;
    for (; i + 4 < deg; i += 8) {
        const int2 ea = bkt[i];
        const int2 eb = bkt[i + 4];
        const uint4 ha = *(const uint4*)(g_xwh + (size_t)ea.x * F_OUT + s * 8);
        const uint4 hb = *(const uint4*)(g_xwh + (size_t)eb.x * F_OUT + s * 8);
        const float va = __int_as_float(ea.y);
        const float vb = __int_as_float(eb.y);
        const __half2* pa = (const __half2*)&ha;
        const __half2* pb = (const __half2*)&hb;
#pragma unroll
        for (int k = 0; k < 4; k++) {
            const float2 fa = __half22float2(pa[k]);
            acc[2 * k]     += va * fa.x;
            acc[2 * k + 1] += va * fa.y;
        }
#pragma unroll
        for (int k = 0; k < 4; k++) {
            const float2 fb = __half22float2(pb[k]);
            acc[2 * k]     += vb * fb.x;
            acc[2 * k + 1] += vb * fb.y;
        }
    }
    if (i < deg) {
        const int2 ea = bkt[i];
        const uint4 ha = *(const uint4*)(g_xwh + (size_t)ea.x * F_OUT + s * 8);
        const float va = __int_as_float(ea.y);
        const __half2* pa = (const __half2*)&ha;
#pragma unroll
        for (int k = 0; k < 4; k++) {
            const float2 fa = __half22float2(pa[k]);
            acc[2 * k]     += va * fa.x;
            acc[2 * k + 1] += va * fa.y;
        }
    }

#pragma unroll
    for (int m = 8; m <= 16; m <<= 1)
#pragma unroll
        for (int k = 0; k < 8; k++)
            acc[k] += __shfl_xor_sync(0xffffffffu, acc[k], m);

    if (g == 0) {
        float* dst = out + (size_t)row * F_OUT + s * 8;
        *(float4*)(dst)     = make_float4(acc[0], acc[1], acc[2], acc[3]);
        *(float4*)(dst + 4) = make_float4(acc[4], acc[5], acc[6], acc[7]);
    }
}

// ===========================================================================
// Launch: memset counts -> fused (GEMM || fill) -> gather.  3 graph nodes.
// ===========================================================================
extern "C" void kernel_launch(void* const* d_in, const int* in_sizes, int n_in,
                              void* d_out, int out_size) {
    const float* X     = (const float*)d_in[0];
    const float* W     = (const float*)d_in[1];
    const int*   erow  = (const int*)d_in[2];
    const int*   ecol  = (const int*)d_in[3];
    const float* evals = (const float*)d_in[4];
    float* out = (float*)d_out;

    void* cnt_ptr = nullptr;
    cudaGetSymbolAddress(&cnt_ptr, g_cnt);
    cudaMemsetAsync(cnt_ptr, 0, N_NODES * sizeof(int));

    fused_gemm_fill_kernel<<<NGB + NFB, 256>>>(X, W, erow, ecol, evals);
    gather_kernel<<<(N_NODES * 32 + 255) / 256, 256>>>(out);
}